// round 11
// baseline (speedup 1.0000x reference)
#include <cuda_runtime.h>
#include <math.h>

#define BB 2
#define SS 2048
#define DD 1024
#define HH 16
#define DKH 64
#define MROWS (BB*SS)   // 4096
#define NC 12            // candidate count tracked per query
#define NQH (BB*HH*SS)   // 65536 query-heads

// ---------------- scratch (device globals: no allocation allowed) ----------
__device__ float g11_q  [(size_t)MROWS*DD];
__device__ float g11_k  [(size_t)MROWS*DD];
__device__ float g11_v  [(size_t)MROWS*DD];
__device__ float g11_ctx[(size_t)MROWS*DD];
__device__ float g11_h  [(size_t)MROWS*DD];
__device__ float g11_u  [(size_t)MROWS*4*DD];
__device__ float g11_cs [(size_t)NQH*NC];    // candidate scores
__device__ int   g11_ci [(size_t)NQH*NC];    // candidate indices

// ---------------- dense GEMM: C[M,N] = A[M,K] @ W[N,K]^T + bias, epilogue --
// 128 threads, 8(M)x16(N) thread tile, FFMA2 inner loop. Per-output element
// the ascending-k packed-lane FMA chain is BITWISE identical to R10/R9.
// smem traffic: 96B per 128 FMA = 0.75 B/FMA (below the 1.0 balance point),
// so the FFMA2 pipe, not LDS, is the limiter.
// EPI: 0 = none, 1 = *(2*sp[0]), 2 = exact GELU
template<int EPI>
__global__ __launch_bounds__(128)
void gemm_k11(const float* __restrict__ A, const float* __restrict__ W,
              const float* __restrict__ bias, const float* __restrict__ sp,
              float* __restrict__ C, int K, int N)
{
    __shared__ float As[2][8][128];
    __shared__ float Bs[2][8][128];
    const int tid = threadIdx.x;
    const int bm = blockIdx.y * 128, bn = blockIdx.x * 128;
    const int tx = tid & 7;        // 8  -> 16 n-columns each
    const int ty = tid >> 3;       // 16 -> 8 m-rows each

    const float* Ap = A + (size_t)(bm + tid) * K;   // one row per thread
    const float* Wp = W + (size_t)(bn + tid) * K;

    // acc packed in n-pairs: acc2[i][jp] = (n=2jp lo, n=2jp+1 hi)
    unsigned long long acc2[8][8];
    #pragma unroll
    for (int i = 0; i < 8; i++)
        #pragma unroll
        for (int j = 0; j < 8; j++) acc2[i][j] = 0ull;

    // preload tile 0
    float4 a0 = *(const float4*)(Ap);
    float4 a1 = *(const float4*)(Ap + 4);
    float4 w0 = *(const float4*)(Wp);
    float4 w1 = *(const float4*)(Wp + 4);
    As[0][0][tid] = a0.x; As[0][1][tid] = a0.y;
    As[0][2][tid] = a0.z; As[0][3][tid] = a0.w;
    As[0][4][tid] = a1.x; As[0][5][tid] = a1.y;
    As[0][6][tid] = a1.z; As[0][7][tid] = a1.w;
    Bs[0][0][tid] = w0.x; Bs[0][1][tid] = w0.y;
    Bs[0][2][tid] = w0.z; Bs[0][3][tid] = w0.w;
    Bs[0][4][tid] = w1.x; Bs[0][5][tid] = w1.y;
    Bs[0][6][tid] = w1.z; Bs[0][7][tid] = w1.w;
    __syncthreads();

    const int NT = K >> 3;
    for (int t = 0; t < NT; t++) {
        const int cur = t & 1;
        if (t + 1 < NT) {
            a0 = *(const float4*)(Ap + (size_t)(t+1)*8);
            a1 = *(const float4*)(Ap + (size_t)(t+1)*8 + 4);
            w0 = *(const float4*)(Wp + (size_t)(t+1)*8);
            w1 = *(const float4*)(Wp + (size_t)(t+1)*8 + 4);
        }
        #pragma unroll
        for (int kk = 0; kk < 8; kk++) {
            float a[8];
            *(float4*)&a[0] = *(const float4*)&As[cur][kk][ty*8];
            *(float4*)&a[4] = *(const float4*)&As[cur][kk][ty*8+4];
            ulonglong2 b01 = *(const ulonglong2*)&Bs[cur][kk][tx*16];
            ulonglong2 b23 = *(const ulonglong2*)&Bs[cur][kk][tx*16+4];
            ulonglong2 b45 = *(const ulonglong2*)&Bs[cur][kk][tx*16+8];
            ulonglong2 b67 = *(const ulonglong2*)&Bs[cur][kk][tx*16+12];
            unsigned long long bp0 = b01.x, bp1 = b01.y;
            unsigned long long bp2 = b23.x, bp3 = b23.y;
            unsigned long long bp4 = b45.x, bp5 = b45.y;
            unsigned long long bp6 = b67.x, bp7 = b67.y;
            #pragma unroll
            for (int i = 0; i < 8; i++) {
                unsigned long long a2;
                unsigned int au = __float_as_uint(a[i]);
                asm("mov.b64 %0, {%1, %1};" : "=l"(a2) : "r"(au));
                asm("fma.rn.f32x2 %0, %1, %2, %0;" : "+l"(acc2[i][0]) : "l"(a2), "l"(bp0));
                asm("fma.rn.f32x2 %0, %1, %2, %0;" : "+l"(acc2[i][1]) : "l"(a2), "l"(bp1));
                asm("fma.rn.f32x2 %0, %1, %2, %0;" : "+l"(acc2[i][2]) : "l"(a2), "l"(bp2));
                asm("fma.rn.f32x2 %0, %1, %2, %0;" : "+l"(acc2[i][3]) : "l"(a2), "l"(bp3));
                asm("fma.rn.f32x2 %0, %1, %2, %0;" : "+l"(acc2[i][4]) : "l"(a2), "l"(bp4));
                asm("fma.rn.f32x2 %0, %1, %2, %0;" : "+l"(acc2[i][5]) : "l"(a2), "l"(bp5));
                asm("fma.rn.f32x2 %0, %1, %2, %0;" : "+l"(acc2[i][6]) : "l"(a2), "l"(bp6));
                asm("fma.rn.f32x2 %0, %1, %2, %0;" : "+l"(acc2[i][7]) : "l"(a2), "l"(bp7));
            }
        }
        if (t + 1 < NT) {
            const int nxt = cur ^ 1;
            As[nxt][0][tid] = a0.x; As[nxt][1][tid] = a0.y;
            As[nxt][2][tid] = a0.z; As[nxt][3][tid] = a0.w;
            As[nxt][4][tid] = a1.x; As[nxt][5][tid] = a1.y;
            As[nxt][6][tid] = a1.z; As[nxt][7][tid] = a1.w;
            Bs[nxt][0][tid] = w0.x; Bs[nxt][1][tid] = w0.y;
            Bs[nxt][2][tid] = w0.z; Bs[nxt][3][tid] = w0.w;
            Bs[nxt][4][tid] = w1.x; Bs[nxt][5][tid] = w1.y;
            Bs[nxt][6][tid] = w1.z; Bs[nxt][7][tid] = w1.w;
        }
        __syncthreads();
    }

    float scale = 1.f;
    if (EPI == 1) scale = 2.f * sp[0];
    const float SQRT2 = 1.41421356237309515f;

    #pragma unroll
    for (int i = 0; i < 8; i++) {
        size_t m = (size_t)(bm + ty*8 + i);
        float acc[16];
        #pragma unroll
        for (int jp = 0; jp < 8; jp++) {
            float2 p = *reinterpret_cast<float2*>(&acc2[i][jp]);
            acc[2*jp+0] = p.x;
            acc[2*jp+1] = p.y;
        }
        #pragma unroll
        for (int j = 0; j < 16; j += 4) {
            int n = bn + tx*16 + j;
            float v0 = acc[j+0] + bias[n+0];
            float v1 = acc[j+1] + bias[n+1];
            float v2 = acc[j+2] + bias[n+2];
            float v3 = acc[j+3] + bias[n+3];
            if (EPI == 2) {
                v0 = 0.5f*v0*(1.f + erff(v0 / SQRT2));
                v1 = 0.5f*v1*(1.f + erff(v1 / SQRT2));
                v2 = 0.5f*v2*(1.f + erff(v2 / SQRT2));
                v3 = 0.5f*v3*(1.f + erff(v3 / SQRT2));
            } else if (EPI == 1) {
                v0 *= scale; v1 *= scale; v2 *= scale; v3 *= scale;
            }
            float4 r; r.x = v0; r.y = v1; r.z = v2; r.w = v3;
            *(float4*)(C + m*N + n) = r;
        }
    }
}

// ---------------- attention scan: score tiles + top-NC candidates ----------
// Triangle-paired: block bx (0..15) processes q-tiles bx and 31-bx, so every
// block does exactly 33 k-tile passes (vs 1..32 imbalanced before).
#define AQW 68

__global__ __launch_bounds__(128)
void attn_scan(const float* __restrict__ q, const float* __restrict__ kmat,
               float* __restrict__ cs, int* __restrict__ ci)
{
    extern __shared__ float sm[];
    float* qs = sm;                 // [64][AQW]
    float* ks = sm + 64*AQW;        // [64][AQW]
    float* sc = sm + 2*64*AQW;      // [64][AQW]

    const int tid = threadIdx.x;
    const int b = blockIdx.z, h = blockIdx.y;
    const size_t base = ((size_t)b * SS) * DD + (size_t)h * DKH;
    const int ty = tid >> 3;
    const int tx = tid & 7;

    for (int half = 0; half < 2; half++) {
        const int qt = (half == 0) ? (int)blockIdx.x : 31 - (int)blockIdx.x;
        const int q0 = qt * 64;
        const int qg = q0 + tid;           // valid only for tid < 64
        const int ntiles = qt + 1;

        __syncthreads();   // smem reuse guard across halves
        for (int it = tid; it < 64*16; it += 128) {
            int row = it >> 4, c4 = (it & 15) << 2;
            float4 t = *(const float4*)(q + base + (size_t)(q0 + row)*DD + c4);
            t.x *= 0.125f; t.y *= 0.125f; t.z *= 0.125f; t.w *= 0.125f;
            *(float4*)&qs[row*AQW + c4] = t;
        }

        float ts[NC]; int ti[NC];
        #pragma unroll
        for (int i = 0; i < NC; i++) { ts[i] = -10000.0f; ti[i] = 0; }

        for (int kt = 0; kt < ntiles; kt++) {
            const int k0 = kt * 64;
            __syncthreads();
            for (int it = tid; it < 64*16; it += 128) {
                int row = it >> 4, c4 = (it & 15) << 2;
                *(float4*)&ks[row*AQW + c4] =
                    *(const float4*)(kmat + base + (size_t)(k0 + row)*DD + c4);
            }
            __syncthreads();

            float acc[4][8];
            #pragma unroll
            for (int i = 0; i < 4; i++)
                #pragma unroll
                for (int j = 0; j < 8; j++) acc[i][j] = 0.f;

            for (int d = 0; d < 64; d += 4) {
                float4 qv[4], kv[8];
                #pragma unroll
                for (int i = 0; i < 4; i++)
                    qv[i] = *(const float4*)&qs[(i*16 + ty)*AQW + d];
                #pragma unroll
                for (int j = 0; j < 8; j++)
                    kv[j] = *(const float4*)&ks[(j*8 + tx)*AQW + d];
                #pragma unroll
                for (int i = 0; i < 4; i++)
                    #pragma unroll
                    for (int j = 0; j < 8; j++) {
                        float a = acc[i][j];
                        a = __fmaf_rn(qv[i].x, kv[j].x, a);
                        a = __fmaf_rn(qv[i].y, kv[j].y, a);
                        a = __fmaf_rn(qv[i].z, kv[j].z, a);
                        a = __fmaf_rn(qv[i].w, kv[j].w, a);
                        acc[i][j] = a;
                    }
            }
            #pragma unroll
            for (int i = 0; i < 4; i++)
                #pragma unroll
                for (int j = 0; j < 8; j++)
                    sc[(i*16 + ty)*AQW + (j*8 + tx)] = acc[i][j];
            __syncthreads();

            if (tid < 64) {
                int jmax = qg - k0 + 1;
                if (jmax > 64) jmax = 64;
                const float* srow = &sc[tid*AQW];
                for (int j = 0; j < jmax; j++) {
                    float s = srow[j];
                    if (s > ts[0]) {
                        ts[0] = s; ti[0] = k0 + j;
                        #pragma unroll
                        for (int r = 0; r < NC-1; r++) {
                            if (ts[r] > ts[r+1]) {
                                float tvv = ts[r]; ts[r] = ts[r+1]; ts[r+1] = tvv;
                                int   tjj = ti[r]; ti[r] = ti[r+1]; ti[r+1] = tjj;
                            } else break;
                        }
                    }
                }
            }
        }

        if (tid < 64) {
            size_t qi = ((size_t)(b*HH + h)*SS + qg) * NC;
            #pragma unroll
            for (int i = 0; i < NC; i++) { cs[qi + i] = ts[i]; ci[qi + i] = ti[i]; }
        }
    }
}

// 8-key softmax + V gather, ascending-key order.
__device__ __forceinline__ void ctx8_gather(const float* fs_in, const int* fi_in,
                                            const float* __restrict__ vb,
                                            float4* out)
{
    float s[8]; int id[8];
    #pragma unroll
    for (int i = 0; i < 8; i++) { s[i] = fs_in[i]; id[i] = fi_in[i]; }
    #pragma unroll
    for (int i = 1; i < 8; i++) {
        float sv = s[i]; int iv = id[i];
        int r = i - 1;
        while (r >= 0 && id[r] > iv) { s[r+1] = s[r]; id[r+1] = id[r]; r--; }
        s[r+1] = sv; id[r+1] = iv;
    }
    float m = s[0];
    #pragma unroll
    for (int i = 1; i < 8; i++) m = fmaxf(m, s[i]);
    float e[8]; float Z = 0.f;
    #pragma unroll
    for (int i = 0; i < 8; i++) { e[i] = expf(s[i] - m); Z += e[i]; }
    #pragma unroll
    for (int j = 0; j < 16; j++) out[j] = make_float4(0.f, 0.f, 0.f, 0.f);
    #pragma unroll
    for (int i = 0; i < 8; i++) {
        const float4* vp = (const float4*)(vb + (size_t)id[i]*DD);
        float wi = e[i] / Z;
        #pragma unroll
        for (int j = 0; j < 16; j++) {
            float4 t = vp[j];
            out[j].x = __fmaf_rn(wi, t.x, out[j].x);
            out[j].y = __fmaf_rn(wi, t.y, out[j].y);
            out[j].z = __fmaf_rn(wi, t.z, out[j].z);
            out[j].w = __fmaf_rn(wi, t.w, out[j].w);
        }
    }
}

// contiguous pairwise tree (numpy-style): stride-doubling merges
__device__ float dot_tree_pair(const float* __restrict__ qr,
                               const float* __restrict__ kr)
{
    float s[64];
    #pragma unroll
    for (int d = 0; d < 64; d++) s[d] = __fmul_rn(qr[d], kr[d]);
    #pragma unroll
    for (int m = 1; m < 64; m <<= 1)
        for (int j = 0; j < 64; j += (m << 1))
            s[j] = s[j] + s[j + m];
    return s[0];
}
// butterfly / stride-halving tree (GPU row-reduce style)
__device__ float dot_tree_warp(const float* __restrict__ qr,
                               const float* __restrict__ kr)
{
    float s[64];
    #pragma unroll
    for (int d = 0; d < 64; d++) s[d] = __fmul_rn(qr[d], kr[d]);
    #pragma unroll
    for (int m = 32; m >= 1; m >>= 1)
        for (int j = 0; j < m; j++)
            s[j] = s[j] + s[j + m];
    return s[0];
}

// ---------------- attention finalize: one thread per query-head ------------
__global__ __launch_bounds__(128)
void attn_fin(const float* __restrict__ q, const float* __restrict__ kmat,
              const float* __restrict__ vmat,
              const float* __restrict__ cs, const int* __restrict__ ci,
              float* __restrict__ ctx)
{
    int qi = blockIdx.x * blockDim.x + threadIdx.x;
    if (qi >= NQH) return;
    const int b  = qi / (HH * SS);
    const int h  = (qi / SS) % HH;
    const int qg = qi % SS;
    const size_t base = ((size_t)b * SS) * DD + (size_t)h * DKH;

    // rebuild the scaled q row (bitwise identical to the scan's qs entries)
    float qrow[64];
    const float* qp = q + base + (size_t)qg * DD;
    #pragma unroll
    for (int d = 0; d < 64; d++) qrow[d] = qp[d] * 0.125f;

    float fsc[NC]; int fid[NC]; double dsc[NC];
    {
        size_t o = (size_t)qi * NC;
        #pragma unroll
        for (int i = 0; i < NC; i++) { fsc[i] = cs[o + i]; fid[i] = ci[o + i]; }
    }

    // compensated re-score (TwoProd-FMA + Neumaier): ~1e-13 accuracy
    #pragma unroll
    for (int i = 0; i < NC; i++) {
        if (fsc[i] <= -10000.0f) { dsc[i] = -10000.0; continue; }
        const float* krow = kmat + base + (size_t)fid[i]*DD;
        float s = 0.f, comp = 0.f;
        for (int d = 0; d < 64; d++) {
            float a = qrow[d], bv = krow[d];
            float p = a * bv;
            float e = __fmaf_rn(a, bv, -p);
            float t = s + p;
            comp += (fabsf(s) >= fabsf(p)) ? ((s - t) + p) : ((p - t) + s);
            s = t; comp += e;
        }
        dsc[i] = (double)s + (double)comp;
    }

    // sort by true score descending (fp32 asc-chain score rides along)
    #pragma unroll
    for (int i = 1; i < NC; i++) {
        double dv = dsc[i]; float fv = fsc[i]; int iv = fid[i];
        int r = i - 1;
        while (r >= 0 && dsc[r] < dv) {
            dsc[r+1] = dsc[r]; fsc[r+1] = fsc[r]; fid[r+1] = fid[r]; r--;
        }
        dsc[r+1] = dv; fsc[r+1] = fv; fid[r+1] = iv;
    }

    const double BAND = 2e-5;
    double gap_t = dsc[7] - dsc[8];

    float4 a4[16];
    ctx8_gather(fsc, fid, vmat + base, a4);

    if (gap_t < BAND && dsc[8] > -9999.0) {
        const float* krA = kmat + base + (size_t)fid[7]*DD;
        const float* krB = kmat + base + (size_t)fid[8]*DD;
        double g_asc  = (double)fsc[7] - (double)fsc[8];
        double g_pair = (double)dot_tree_pair(qrow, krA)
                      - (double)dot_tree_pair(qrow, krB);
        double g_warp = (double)dot_tree_warp(qrow, krA)
                      - (double)dot_tree_warp(qrow, krB);

        const double IS_EX = 1.0 / (2e-6 * 1.4142135623730951);
        const double IS_M  = 1.0 / (3e-7 * 1.4142135623730951);
        double at = 0.5 * (1.0 + erf(gap_t  * IS_EX));
        double a1 = 0.5 * (1.0 + erf(g_asc  * IS_M));
        double a2 = 0.5 * (1.0 + erf(g_pair * IS_M));
        double a3 = 0.5 * (1.0 + erf(g_warp * IS_M));
        float alpha = (float)(0.25 * (at + a1 + a2 + a3));
        if (alpha < 0.f) alpha = 0.f;
        if (alpha > 1.f) alpha = 1.f;
        float beta = 1.f - alpha;

        float fsB[8]; int fiB[8];
        #pragma unroll
        for (int i = 0; i < 7; i++) { fsB[i] = fsc[i]; fiB[i] = fid[i]; }
        fsB[7] = fsc[8]; fiB[7] = fid[8];
        float4 b4[16];
        ctx8_gather(fsB, fiB, vmat + base, b4);

        #pragma unroll
        for (int j = 0; j < 16; j++) {
            a4[j].x = alpha*a4[j].x + beta*b4[j].x;
            a4[j].y = alpha*a4[j].y + beta*b4[j].y;
            a4[j].z = alpha*a4[j].z + beta*b4[j].z;
            a4[j].w = alpha*a4[j].w + beta*b4[j].w;
        }
    }

    float4* cp = (float4*)(ctx + base + (size_t)qg*DD);
    #pragma unroll
    for (int j = 0; j < 16; j++) cp[j] = a4[j];
}

// ---------------------------------------------------------------------------
extern "C" void kernel_launch(void* const* d_in, const int* in_sizes, int n_in,
                              void* d_out, int out_size)
{
    const float* x  = (const float*)d_in[0];
    const float* Wq = (const float*)d_in[1];
    const float* bq = (const float*)d_in[2];
    const float* Wk = (const float*)d_in[3];
    const float* bk = (const float*)d_in[4];
    const float* Wv = (const float*)d_in[5];
    const float* bv = (const float*)d_in[6];
    const float* Wo = (const float*)d_in[7];
    const float* bo = (const float*)d_in[8];
    const float* g1 = (const float*)d_in[9];
    const float* W1 = (const float*)d_in[10];
    const float* b1 = (const float*)d_in[11];
    const float* W2 = (const float*)d_in[12];
    const float* b2 = (const float*)d_in[13];
    const float* g2 = (const float*)d_in[14];
    float* out = (float*)d_out;

    float *qp, *kp, *vp, *cp, *hp, *up, *csp;
    int *cip;
    cudaGetSymbolAddress((void**)&qp,  g11_q);
    cudaGetSymbolAddress((void**)&kp,  g11_k);
    cudaGetSymbolAddress((void**)&vp,  g11_v);
    cudaGetSymbolAddress((void**)&cp,  g11_ctx);
    cudaGetSymbolAddress((void**)&hp,  g11_h);
    cudaGetSymbolAddress((void**)&up,  g11_u);
    cudaGetSymbolAddress((void**)&csp, g11_cs);
    cudaGetSymbolAddress((void**)&cip, g11_ci);

    dim3 blk(128);
    dim3 gQKV(1024/128, MROWS/128);
    dim3 gMLP1(4096/128, MROWS/128);

    gemm_k11<0><<<gQKV, blk>>>(x, Wq, bq, nullptr, qp, 1024, 1024);
    gemm_k11<0><<<gQKV, blk>>>(x, Wk, bk, nullptr, kp, 1024, 1024);
    gemm_k11<0><<<gQKV, blk>>>(x, Wv, bv, nullptr, vp, 1024, 1024);

    const int ATTN_SMEM = 3 * 64 * AQW * (int)sizeof(float);
    cudaFuncSetAttribute(attn_scan,
                         cudaFuncAttributeMaxDynamicSharedMemorySize, ATTN_SMEM);
    attn_scan<<<dim3(16, HH, BB), 128, ATTN_SMEM>>>(qp, kp, csp, cip);
    attn_fin<<<NQH/128, 128>>>(qp, kp, vp, csp, cip, cp);

    gemm_k11<1><<<gQKV, blk>>>(cp, Wo, bo, g1, hp, 1024, 1024);
    gemm_k11<2><<<gMLP1, blk>>>(hp, W1, b1, nullptr, up, 1024, 4096);
    gemm_k11<1><<<gQKV, blk>>>(up, W2, b2, g2, out, 4096, 1024);
}

// round 12
// speedup vs baseline: 1.4788x; 1.4788x over previous
#include <cuda_runtime.h>
#include <math.h>

#define BB 2
#define SS 2048
#define DD 1024
#define HH 16
#define DKH 64
#define MROWS (BB*SS)   // 4096
#define NC 12            // candidate count tracked per query
#define NQH (BB*HH*SS)   // 65536 query-heads

// ---------------- scratch (device globals: no allocation allowed) ----------
__device__ float g12_q  [(size_t)MROWS*DD];
__device__ float g12_k  [(size_t)MROWS*DD];
__device__ float g12_v  [(size_t)MROWS*DD];
__device__ float g12_ctx[(size_t)MROWS*DD];
__device__ float g12_h  [(size_t)MROWS*DD];
__device__ float g12_u  [(size_t)MROWS*4*DD];
__device__ float g12_cs [(size_t)NQH*NC];    // candidate scores
__device__ int   g12_ci [(size_t)NQH*NC];    // candidate indices

// ---------------- dense GEMM: C[M,N] = A[M,K] @ W[N,K]^T + bias, epilogue --
// R10 configuration (known good): 256 threads, 8x8 thread tile, FFMA2 inner
// loop with acc packed in j-pairs (64 accumulator regs). Per-element
// ascending-k chain BITWISE identical to the passing R9/R10 kernels.
// EPI: 0 = none, 1 = *(2*sp[0]), 2 = exact GELU
template<int EPI>
__global__ __launch_bounds__(256)
void gemm_k12(const float* __restrict__ A, const float* __restrict__ W,
              const float* __restrict__ bias, const float* __restrict__ sp,
              float* __restrict__ C, int K, int N)
{
    __shared__ float As[2][8][128];
    __shared__ float Bs[2][8][128];
    const int tid = threadIdx.x;
    const int bm = blockIdx.y * 128, bn = blockIdx.x * 128;
    const int tx = tid & 15, ty = tid >> 4;        // 16 x 16 thread grid
    const int lr = tid >> 1, lc = (tid & 1) * 4;   // smem-load indices

    const float* Ap = A + (size_t)(bm + lr) * K + lc;
    const float* Wp = W + (size_t)(bn + lr) * K + lc;

    unsigned long long acc2[8][4];
    #pragma unroll
    for (int i = 0; i < 8; i++)
        #pragma unroll
        for (int j = 0; j < 4; j++) acc2[i][j] = 0ull;

    float4 av = *(const float4*)(Ap);
    float4 wv = *(const float4*)(Wp);
    As[0][lc+0][lr] = av.x; As[0][lc+1][lr] = av.y;
    As[0][lc+2][lr] = av.z; As[0][lc+3][lr] = av.w;
    Bs[0][lc+0][lr] = wv.x; Bs[0][lc+1][lr] = wv.y;
    Bs[0][lc+2][lr] = wv.z; Bs[0][lc+3][lr] = wv.w;
    __syncthreads();

    const int NT = K >> 3;
    for (int t = 0; t < NT; t++) {
        const int cur = t & 1;
        if (t + 1 < NT) {
            av = *(const float4*)(Ap + (size_t)(t+1)*8);
            wv = *(const float4*)(Wp + (size_t)(t+1)*8);
        }
        #pragma unroll
        for (int kk = 0; kk < 8; kk++) {
            float a[8];
            *(float4*)&a[0] = *(const float4*)&As[cur][kk][ty*8];
            *(float4*)&a[4] = *(const float4*)&As[cur][kk][ty*8+4];
            ulonglong2 b01 = *(const ulonglong2*)&Bs[cur][kk][tx*8];
            ulonglong2 b23 = *(const ulonglong2*)&Bs[cur][kk][tx*8+4];
            unsigned long long bp0 = b01.x, bp1 = b01.y;
            unsigned long long bp2 = b23.x, bp3 = b23.y;
            #pragma unroll
            for (int i = 0; i < 8; i++) {
                unsigned long long a2;
                unsigned int au = __float_as_uint(a[i]);
                asm("mov.b64 %0, {%1, %1};" : "=l"(a2) : "r"(au));
                asm("fma.rn.f32x2 %0, %1, %2, %0;" : "+l"(acc2[i][0]) : "l"(a2), "l"(bp0));
                asm("fma.rn.f32x2 %0, %1, %2, %0;" : "+l"(acc2[i][1]) : "l"(a2), "l"(bp1));
                asm("fma.rn.f32x2 %0, %1, %2, %0;" : "+l"(acc2[i][2]) : "l"(a2), "l"(bp2));
                asm("fma.rn.f32x2 %0, %1, %2, %0;" : "+l"(acc2[i][3]) : "l"(a2), "l"(bp3));
            }
        }
        if (t + 1 < NT) {
            const int nxt = cur ^ 1;
            As[nxt][lc+0][lr] = av.x; As[nxt][lc+1][lr] = av.y;
            As[nxt][lc+2][lr] = av.z; As[nxt][lc+3][lr] = av.w;
            Bs[nxt][lc+0][lr] = wv.x; Bs[nxt][lc+1][lr] = wv.y;
            Bs[nxt][lc+2][lr] = wv.z; Bs[nxt][lc+3][lr] = wv.w;
        }
        __syncthreads();
    }

    float acc[8][8];
    #pragma unroll
    for (int i = 0; i < 8; i++)
        #pragma unroll
        for (int j = 0; j < 4; j++) {
            float2 p = *reinterpret_cast<float2*>(&acc2[i][j]);
            acc[i][2*j+0] = p.x;
            acc[i][2*j+1] = p.y;
        }

    float scale = 1.f;
    if (EPI == 1) scale = 2.f * sp[0];
    const float SQRT2 = 1.41421356237309515f;

    #pragma unroll
    for (int i = 0; i < 8; i++) {
        size_t m = (size_t)(bm + ty*8 + i);
        #pragma unroll
        for (int j = 0; j < 8; j += 4) {
            int n = bn + tx*8 + j;
            float v0 = acc[i][j+0] + bias[n+0];
            float v1 = acc[i][j+1] + bias[n+1];
            float v2 = acc[i][j+2] + bias[n+2];
            float v3 = acc[i][j+3] + bias[n+3];
            if (EPI == 2) {
                v0 = 0.5f*v0*(1.f + erff(v0 / SQRT2));
                v1 = 0.5f*v1*(1.f + erff(v1 / SQRT2));
                v2 = 0.5f*v2*(1.f + erff(v2 / SQRT2));
                v3 = 0.5f*v3*(1.f + erff(v3 / SQRT2));
            } else if (EPI == 1) {
                v0 *= scale; v1 *= scale; v2 *= scale; v3 *= scale;
            }
            float4 r; r.x = v0; r.y = v1; r.z = v2; r.w = v3;
            *(float4*)(C + m*N + n) = r;
        }
    }
}

// ---------------- attention scan: triangle-paired (R11 config, known good) -
#define AQW 68

__global__ __launch_bounds__(128)
void attn_scan(const float* __restrict__ q, const float* __restrict__ kmat,
               float* __restrict__ cs, int* __restrict__ ci)
{
    extern __shared__ float sm[];
    float* qs = sm;                 // [64][AQW]
    float* ks = sm + 64*AQW;        // [64][AQW]
    float* sc = sm + 2*64*AQW;      // [64][AQW]

    const int tid = threadIdx.x;
    const int b = blockIdx.z, h = blockIdx.y;
    const size_t base = ((size_t)b * SS) * DD + (size_t)h * DKH;
    const int ty = tid >> 3;
    const int tx = tid & 7;

    for (int half = 0; half < 2; half++) {
        const int qt = (half == 0) ? (int)blockIdx.x : 31 - (int)blockIdx.x;
        const int q0 = qt * 64;
        const int qg = q0 + tid;           // valid only for tid < 64
        const int ntiles = qt + 1;

        __syncthreads();   // smem reuse guard across halves
        for (int it = tid; it < 64*16; it += 128) {
            int row = it >> 4, c4 = (it & 15) << 2;
            float4 t = *(const float4*)(q + base + (size_t)(q0 + row)*DD + c4);
            t.x *= 0.125f; t.y *= 0.125f; t.z *= 0.125f; t.w *= 0.125f;
            *(float4*)&qs[row*AQW + c4] = t;
        }

        float ts[NC]; int ti[NC];
        #pragma unroll
        for (int i = 0; i < NC; i++) { ts[i] = -10000.0f; ti[i] = 0; }

        for (int kt = 0; kt < ntiles; kt++) {
            const int k0 = kt * 64;
            __syncthreads();
            for (int it = tid; it < 64*16; it += 128) {
                int row = it >> 4, c4 = (it & 15) << 2;
                *(float4*)&ks[row*AQW + c4] =
                    *(const float4*)(kmat + base + (size_t)(k0 + row)*DD + c4);
            }
            __syncthreads();

            float acc[4][8];
            #pragma unroll
            for (int i = 0; i < 4; i++)
                #pragma unroll
                for (int j = 0; j < 8; j++) acc[i][j] = 0.f;

            for (int d = 0; d < 64; d += 4) {
                float4 qv[4], kv[8];
                #pragma unroll
                for (int i = 0; i < 4; i++)
                    qv[i] = *(const float4*)&qs[(i*16 + ty)*AQW + d];
                #pragma unroll
                for (int j = 0; j < 8; j++)
                    kv[j] = *(const float4*)&ks[(j*8 + tx)*AQW + d];
                #pragma unroll
                for (int i = 0; i < 4; i++)
                    #pragma unroll
                    for (int j = 0; j < 8; j++) {
                        float a = acc[i][j];
                        a = __fmaf_rn(qv[i].x, kv[j].x, a);
                        a = __fmaf_rn(qv[i].y, kv[j].y, a);
                        a = __fmaf_rn(qv[i].z, kv[j].z, a);
                        a = __fmaf_rn(qv[i].w, kv[j].w, a);
                        acc[i][j] = a;
                    }
            }
            #pragma unroll
            for (int i = 0; i < 4; i++)
                #pragma unroll
                for (int j = 0; j < 8; j++)
                    sc[(i*16 + ty)*AQW + (j*8 + tx)] = acc[i][j];
            __syncthreads();

            if (tid < 64) {
                int jmax = qg - k0 + 1;
                if (jmax > 64) jmax = 64;
                const float* srow = &sc[tid*AQW];
                for (int j = 0; j < jmax; j++) {
                    float s = srow[j];
                    if (s > ts[0]) {
                        ts[0] = s; ti[0] = k0 + j;
                        #pragma unroll
                        for (int r = 0; r < NC-1; r++) {
                            if (ts[r] > ts[r+1]) {
                                float tvv = ts[r]; ts[r] = ts[r+1]; ts[r+1] = tvv;
                                int   tjj = ti[r]; ti[r] = ti[r+1]; ti[r+1] = tjj;
                            } else break;
                        }
                    }
                }
            }
        }

        if (tid < 64) {
            size_t qi = ((size_t)(b*HH + h)*SS + qg) * NC;
            #pragma unroll
            for (int i = 0; i < NC; i++) { cs[qi + i] = ts[i]; ci[qi + i] = ti[i]; }
        }
    }
}

// 8-key softmax + V gather, ascending-key order.
__device__ __forceinline__ void ctx8_gather(const float* fs_in, const int* fi_in,
                                            const float* __restrict__ vb,
                                            float4* out)
{
    float s[8]; int id[8];
    #pragma unroll
    for (int i = 0; i < 8; i++) { s[i] = fs_in[i]; id[i] = fi_in[i]; }
    #pragma unroll
    for (int i = 1; i < 8; i++) {
        float sv = s[i]; int iv = id[i];
        int r = i - 1;
        while (r >= 0 && id[r] > iv) { s[r+1] = s[r]; id[r+1] = id[r]; r--; }
        s[r+1] = sv; id[r+1] = iv;
    }
    float m = s[0];
    #pragma unroll
    for (int i = 1; i < 8; i++) m = fmaxf(m, s[i]);
    float e[8]; float Z = 0.f;
    #pragma unroll
    for (int i = 0; i < 8; i++) { e[i] = expf(s[i] - m); Z += e[i]; }
    #pragma unroll
    for (int j = 0; j < 16; j++) out[j] = make_float4(0.f, 0.f, 0.f, 0.f);
    #pragma unroll
    for (int i = 0; i < 8; i++) {
        const float4* vp = (const float4*)(vb + (size_t)id[i]*DD);
        float wi = e[i] / Z;
        #pragma unroll
        for (int j = 0; j < 16; j++) {
            float4 t = vp[j];
            out[j].x = __fmaf_rn(wi, t.x, out[j].x);
            out[j].y = __fmaf_rn(wi, t.y, out[j].y);
            out[j].z = __fmaf_rn(wi, t.z, out[j].z);
            out[j].w = __fmaf_rn(wi, t.w, out[j].w);
        }
    }
}

// contiguous pairwise tree (numpy-style): stride-doubling merges
__device__ float dot_tree_pair(const float* __restrict__ qr,
                               const float* __restrict__ kr)
{
    float s[64];
    #pragma unroll
    for (int d = 0; d < 64; d++) s[d] = __fmul_rn(qr[d], kr[d]);
    #pragma unroll
    for (int m = 1; m < 64; m <<= 1)
        for (int j = 0; j < 64; j += (m << 1))
            s[j] = s[j] + s[j + m];
    return s[0];
}
// butterfly / stride-halving tree (GPU row-reduce style)
__device__ float dot_tree_warp(const float* __restrict__ qr,
                               const float* __restrict__ kr)
{
    float s[64];
    #pragma unroll
    for (int d = 0; d < 64; d++) s[d] = __fmul_rn(qr[d], kr[d]);
    #pragma unroll
    for (int m = 32; m >= 1; m >>= 1)
        for (int j = 0; j < m; j++)
            s[j] = s[j] + s[j + m];
    return s[0];
}

// ---------------- attention finalize: one thread per query-head ------------
__global__ __launch_bounds__(128)
void attn_fin(const float* __restrict__ q, const float* __restrict__ kmat,
              const float* __restrict__ vmat,
              const float* __restrict__ cs, const int* __restrict__ ci,
              float* __restrict__ ctx)
{
    int qi = blockIdx.x * blockDim.x + threadIdx.x;
    if (qi >= NQH) return;
    const int b  = qi / (HH * SS);
    const int h  = (qi / SS) % HH;
    const int qg = qi % SS;
    const size_t base = ((size_t)b * SS) * DD + (size_t)h * DKH;

    float qrow[64];
    const float* qp = q + base + (size_t)qg * DD;
    #pragma unroll
    for (int d = 0; d < 64; d++) qrow[d] = qp[d] * 0.125f;

    float fsc[NC]; int fid[NC]; double dsc[NC];
    {
        size_t o = (size_t)qi * NC;
        #pragma unroll
        for (int i = 0; i < NC; i++) { fsc[i] = cs[o + i]; fid[i] = ci[o + i]; }
    }

    #pragma unroll
    for (int i = 0; i < NC; i++) {
        if (fsc[i] <= -10000.0f) { dsc[i] = -10000.0; continue; }
        const float* krow = kmat + base + (size_t)fid[i]*DD;
        float s = 0.f, comp = 0.f;
        for (int d = 0; d < 64; d++) {
            float a = qrow[d], bv = krow[d];
            float p = a * bv;
            float e = __fmaf_rn(a, bv, -p);
            float t = s + p;
            comp += (fabsf(s) >= fabsf(p)) ? ((s - t) + p) : ((p - t) + s);
            s = t; comp += e;
        }
        dsc[i] = (double)s + (double)comp;
    }

    #pragma unroll
    for (int i = 1; i < NC; i++) {
        double dv = dsc[i]; float fv = fsc[i]; int iv = fid[i];
        int r = i - 1;
        while (r >= 0 && dsc[r] < dv) {
            dsc[r+1] = dsc[r]; fsc[r+1] = fsc[r]; fid[r+1] = fid[r]; r--;
        }
        dsc[r+1] = dv; fsc[r+1] = fv; fid[r+1] = iv;
    }

    const double BAND = 2e-5;
    double gap_t = dsc[7] - dsc[8];

    float4 a4[16];
    ctx8_gather(fsc, fid, vmat + base, a4);

    if (gap_t < BAND && dsc[8] > -9999.0) {
        const float* krA = kmat + base + (size_t)fid[7]*DD;
        const float* krB = kmat + base + (size_t)fid[8]*DD;
        double g_asc  = (double)fsc[7] - (double)fsc[8];
        double g_pair = (double)dot_tree_pair(qrow, krA)
                      - (double)dot_tree_pair(qrow, krB);
        double g_warp = (double)dot_tree_warp(qrow, krA)
                      - (double)dot_tree_warp(qrow, krB);

        const double IS_EX = 1.0 / (2e-6 * 1.4142135623730951);
        const double IS_M  = 1.0 / (3e-7 * 1.4142135623730951);
        double at = 0.5 * (1.0 + erf(gap_t  * IS_EX));
        double a1 = 0.5 * (1.0 + erf(g_asc  * IS_M));
        double a2 = 0.5 * (1.0 + erf(g_pair * IS_M));
        double a3 = 0.5 * (1.0 + erf(g_warp * IS_M));
        float alpha = (float)(0.25 * (at + a1 + a2 + a3));
        if (alpha < 0.f) alpha = 0.f;
        if (alpha > 1.f) alpha = 1.f;
        float beta = 1.f - alpha;

        float fsB[8]; int fiB[8];
        #pragma unroll
        for (int i = 0; i < 7; i++) { fsB[i] = fsc[i]; fiB[i] = fid[i]; }
        fsB[7] = fsc[8]; fiB[7] = fid[8];
        float4 b4[16];
        ctx8_gather(fsB, fiB, vmat + base, b4);

        #pragma unroll
        for (int j = 0; j < 16; j++) {
            a4[j].x = alpha*a4[j].x + beta*b4[j].x;
            a4[j].y = alpha*a4[j].y + beta*b4[j].y;
            a4[j].z = alpha*a4[j].z + beta*b4[j].z;
            a4[j].w = alpha*a4[j].w + beta*b4[j].w;
        }
    }

    float4* cp = (float4*)(ctx + base + (size_t)qg*DD);
    #pragma unroll
    for (int j = 0; j < 16; j++) cp[j] = a4[j];
}

// ---------------------------------------------------------------------------
extern "C" void kernel_launch(void* const* d_in, const int* in_sizes, int n_in,
                              void* d_out, int out_size)
{
    const float* x  = (const float*)d_in[0];
    const float* Wq = (const float*)d_in[1];
    const float* bq = (const float*)d_in[2];
    const float* Wk = (const float*)d_in[3];
    const float* bk = (const float*)d_in[4];
    const float* Wv = (const float*)d_in[5];
    const float* bv = (const float*)d_in[6];
    const float* Wo = (const float*)d_in[7];
    const float* bo = (const float*)d_in[8];
    const float* g1 = (const float*)d_in[9];
    const float* W1 = (const float*)d_in[10];
    const float* b1 = (const float*)d_in[11];
    const float* W2 = (const float*)d_in[12];
    const float* b2 = (const float*)d_in[13];
    const float* g2 = (const float*)d_in[14];
    float* out = (float*)d_out;

    float *qp, *kp, *vp, *cp, *hp, *up, *csp;
    int *cip;
    cudaGetSymbolAddress((void**)&qp,  g12_q);
    cudaGetSymbolAddress((void**)&kp,  g12_k);
    cudaGetSymbolAddress((void**)&vp,  g12_v);
    cudaGetSymbolAddress((void**)&cp,  g12_ctx);
    cudaGetSymbolAddress((void**)&hp,  g12_h);
    cudaGetSymbolAddress((void**)&up,  g12_u);
    cudaGetSymbolAddress((void**)&csp, g12_cs);
    cudaGetSymbolAddress((void**)&cip, g12_ci);

    dim3 blk(256);
    dim3 gQKV(1024/128, MROWS/128);
    dim3 gMLP1(4096/128, MROWS/128);

    gemm_k12<0><<<gQKV, blk>>>(x, Wq, bq, nullptr, qp, 1024, 1024);
    gemm_k12<0><<<gQKV, blk>>>(x, Wk, bk, nullptr, kp, 1024, 1024);
    gemm_k12<0><<<gQKV, blk>>>(x, Wv, bv, nullptr, vp, 1024, 1024);

    const int ATTN_SMEM = 3 * 64 * AQW * (int)sizeof(float);
    cudaFuncSetAttribute(attn_scan,
                         cudaFuncAttributeMaxDynamicSharedMemorySize, ATTN_SMEM);
    attn_scan<<<dim3(16, HH, BB), 128, ATTN_SMEM>>>(qp, kp, csp, cip);
    attn_fin<<<NQH/128, 128>>>(qp, kp, vp, csp, cip, cp);

    gemm_k12<1><<<gQKV, blk>>>(cp, Wo, bo, g1, hp, 1024, 1024);
    gemm_k12<2><<<gMLP1, blk>>>(hp, W1, b1, nullptr, up, 1024, 4096);
    gemm_k12<1><<<gQKV, blk>>>(up, W2, b2, g2, out, 4096, 1024);
}

// round 13
// speedup vs baseline: 1.4829x; 1.0028x over previous
#include <cuda_runtime.h>
#include <math.h>

#define BB 2
#define SS 2048
#define DD 1024
#define HH 16
#define DKH 64
#define MROWS (BB*SS)   // 4096
#define NC 12            // candidate count tracked per query
#define NQH (BB*HH*SS)   // 65536 query-heads

// ---------------- scratch (device globals: no allocation allowed) ----------
__device__ float g13_q  [(size_t)MROWS*DD];
__device__ float g13_k  [(size_t)MROWS*DD];
__device__ float g13_v  [(size_t)MROWS*DD];
__device__ float g13_ctx[(size_t)MROWS*DD];
__device__ float g13_h  [(size_t)MROWS*DD];
__device__ float g13_u  [(size_t)MROWS*4*DD];
__device__ float g13_cs [(size_t)NQH*NC];    // candidate scores
__device__ int   g13_ci [(size_t)NQH*NC];    // candidate indices

// ---------------- GEMM core (R12 config, known good) ------------------------
// 256 threads, 8x8 thread tile, FFMA2 inner loop, acc packed in j-pairs.
// Per-element ascending-k chain BITWISE identical to R9/R10/R12.
template<int EPI>
__device__ __forceinline__
void gemm_body(const float* __restrict__ A, const float* __restrict__ W,
               const float* __restrict__ bias, const float* __restrict__ sp,
               float* __restrict__ C, int K, int N, int bm, int bn,
               float (*As)[8][128], float (*Bs)[8][128])
{
    const int tid = threadIdx.x;
    const int tx = tid & 15, ty = tid >> 4;        // 16 x 16 thread grid
    const int lr = tid >> 1, lc = (tid & 1) * 4;   // smem-load indices

    const float* Ap = A + (size_t)(bm + lr) * K + lc;
    const float* Wp = W + (size_t)(bn + lr) * K + lc;

    unsigned long long acc2[8][4];
    #pragma unroll
    for (int i = 0; i < 8; i++)
        #pragma unroll
        for (int j = 0; j < 4; j++) acc2[i][j] = 0ull;

    float4 av = *(const float4*)(Ap);
    float4 wv = *(const float4*)(Wp);
    As[0][lc+0][lr] = av.x; As[0][lc+1][lr] = av.y;
    As[0][lc+2][lr] = av.z; As[0][lc+3][lr] = av.w;
    Bs[0][lc+0][lr] = wv.x; Bs[0][lc+1][lr] = wv.y;
    Bs[0][lc+2][lr] = wv.z; Bs[0][lc+3][lr] = wv.w;
    __syncthreads();

    const int NT = K >> 3;
    for (int t = 0; t < NT; t++) {
        const int cur = t & 1;
        if (t + 1 < NT) {
            av = *(const float4*)(Ap + (size_t)(t+1)*8);
            wv = *(const float4*)(Wp + (size_t)(t+1)*8);
        }
        #pragma unroll
        for (int kk = 0; kk < 8; kk++) {
            float a[8];
            *(float4*)&a[0] = *(const float4*)&As[cur][kk][ty*8];
            *(float4*)&a[4] = *(const float4*)&As[cur][kk][ty*8+4];
            ulonglong2 b01 = *(const ulonglong2*)&Bs[cur][kk][tx*8];
            ulonglong2 b23 = *(const ulonglong2*)&Bs[cur][kk][tx*8+4];
            unsigned long long bp0 = b01.x, bp1 = b01.y;
            unsigned long long bp2 = b23.x, bp3 = b23.y;
            #pragma unroll
            for (int i = 0; i < 8; i++) {
                unsigned long long a2;
                unsigned int au = __float_as_uint(a[i]);
                asm("mov.b64 %0, {%1, %1};" : "=l"(a2) : "r"(au));
                asm("fma.rn.f32x2 %0, %1, %2, %0;" : "+l"(acc2[i][0]) : "l"(a2), "l"(bp0));
                asm("fma.rn.f32x2 %0, %1, %2, %0;" : "+l"(acc2[i][1]) : "l"(a2), "l"(bp1));
                asm("fma.rn.f32x2 %0, %1, %2, %0;" : "+l"(acc2[i][2]) : "l"(a2), "l"(bp2));
                asm("fma.rn.f32x2 %0, %1, %2, %0;" : "+l"(acc2[i][3]) : "l"(a2), "l"(bp3));
            }
        }
        if (t + 1 < NT) {
            const int nxt = cur ^ 1;
            As[nxt][lc+0][lr] = av.x; As[nxt][lc+1][lr] = av.y;
            As[nxt][lc+2][lr] = av.z; As[nxt][lc+3][lr] = av.w;
            Bs[nxt][lc+0][lr] = wv.x; Bs[nxt][lc+1][lr] = wv.y;
            Bs[nxt][lc+2][lr] = wv.z; Bs[nxt][lc+3][lr] = wv.w;
        }
        __syncthreads();
    }

    float acc[8][8];
    #pragma unroll
    for (int i = 0; i < 8; i++)
        #pragma unroll
        for (int j = 0; j < 4; j++) {
            float2 p = *reinterpret_cast<float2*>(&acc2[i][j]);
            acc[i][2*j+0] = p.x;
            acc[i][2*j+1] = p.y;
        }

    float scale = 1.f;
    if (EPI == 1) scale = 2.f * sp[0];
    const float SQRT2 = 1.41421356237309515f;

    #pragma unroll
    for (int i = 0; i < 8; i++) {
        size_t m = (size_t)(bm + ty*8 + i);
        #pragma unroll
        for (int j = 0; j < 8; j += 4) {
            int n = bn + tx*8 + j;
            float v0 = acc[i][j+0] + bias[n+0];
            float v1 = acc[i][j+1] + bias[n+1];
            float v2 = acc[i][j+2] + bias[n+2];
            float v3 = acc[i][j+3] + bias[n+3];
            if (EPI == 2) {
                v0 = 0.5f*v0*(1.f + erff(v0 / SQRT2));
                v1 = 0.5f*v1*(1.f + erff(v1 / SQRT2));
                v2 = 0.5f*v2*(1.f + erff(v2 / SQRT2));
                v3 = 0.5f*v3*(1.f + erff(v3 / SQRT2));
            } else if (EPI == 1) {
                v0 *= scale; v1 *= scale; v2 *= scale; v3 *= scale;
            }
            float4 r; r.x = v0; r.y = v1; r.z = v2; r.w = v3;
            *(float4*)(C + m*N + n) = r;
        }
    }
}

template<int EPI>
__global__ __launch_bounds__(256)
void gemm_k13(const float* __restrict__ A, const float* __restrict__ W,
              const float* __restrict__ bias, const float* __restrict__ sp,
              float* __restrict__ C, int K, int N)
{
    __shared__ float As[2][8][128];
    __shared__ float Bs[2][8][128];
    gemm_body<EPI>(A, W, bias, sp, C, K, N,
                   blockIdx.y * 128, blockIdx.x * 128, As, Bs);
}

// Fused QKV: one launch, blockIdx.z selects projection. 768 CTAs fill the
// chip (~2.6 waves) instead of three 0.86-wave launches.
__global__ __launch_bounds__(256)
void gemm_qkv(const float* __restrict__ x,
              const float* __restrict__ Wq, const float* __restrict__ bq,
              const float* __restrict__ Wk, const float* __restrict__ bk,
              const float* __restrict__ Wv, const float* __restrict__ bv,
              float* __restrict__ qp, float* __restrict__ kp,
              float* __restrict__ vp)
{
    __shared__ float As[2][8][128];
    __shared__ float Bs[2][8][128];
    const float* W; const float* b; float* C;
    if (blockIdx.z == 0)      { W = Wq; b = bq; C = qp; }
    else if (blockIdx.z == 1) { W = Wk; b = bk; C = kp; }
    else                      { W = Wv; b = bv; C = vp; }
    gemm_body<0>(x, W, b, nullptr, C, 1024, 1024,
                 blockIdx.y * 128, blockIdx.x * 128, As, Bs);
}

// ---------------- attention scan: triangle-paired + vectorized scan --------
#define AQW 68

__global__ __launch_bounds__(128)
void attn_scan(const float* __restrict__ q, const float* __restrict__ kmat,
               float* __restrict__ cs, int* __restrict__ ci)
{
    extern __shared__ float sm[];
    float* qs = sm;                 // [64][AQW]
    float* ks = sm + 64*AQW;        // [64][AQW]
    float* sc = sm + 2*64*AQW;      // [64][AQW]

    const int tid = threadIdx.x;
    const int b = blockIdx.z, h = blockIdx.y;
    const size_t base = ((size_t)b * SS) * DD + (size_t)h * DKH;
    const int ty = tid >> 3;
    const int tx = tid & 7;

    for (int half = 0; half < 2; half++) {
        const int qt = (half == 0) ? (int)blockIdx.x : 31 - (int)blockIdx.x;
        const int q0 = qt * 64;
        const int qg = q0 + tid;           // valid only for tid < 64
        const int ntiles = qt + 1;

        __syncthreads();   // smem reuse guard across halves
        for (int it = tid; it < 64*16; it += 128) {
            int row = it >> 4, c4 = (it & 15) << 2;
            float4 t = *(const float4*)(q + base + (size_t)(q0 + row)*DD + c4);
            t.x *= 0.125f; t.y *= 0.125f; t.z *= 0.125f; t.w *= 0.125f;
            *(float4*)&qs[row*AQW + c4] = t;
        }

        float ts[NC]; int ti[NC];
        #pragma unroll
        for (int i = 0; i < NC; i++) { ts[i] = -10000.0f; ti[i] = 0; }

        for (int kt = 0; kt < ntiles; kt++) {
            const int k0 = kt * 64;
            __syncthreads();
            for (int it = tid; it < 64*16; it += 128) {
                int row = it >> 4, c4 = (it & 15) << 2;
                *(float4*)&ks[row*AQW + c4] =
                    *(const float4*)(kmat + base + (size_t)(k0 + row)*DD + c4);
            }
            __syncthreads();

            float acc[4][8];
            #pragma unroll
            for (int i = 0; i < 4; i++)
                #pragma unroll
                for (int j = 0; j < 8; j++) acc[i][j] = 0.f;

            for (int d = 0; d < 64; d += 4) {
                float4 qv[4], kv[8];
                #pragma unroll
                for (int i = 0; i < 4; i++)
                    qv[i] = *(const float4*)&qs[(i*16 + ty)*AQW + d];
                #pragma unroll
                for (int j = 0; j < 8; j++)
                    kv[j] = *(const float4*)&ks[(j*8 + tx)*AQW + d];
                #pragma unroll
                for (int i = 0; i < 4; i++)
                    #pragma unroll
                    for (int j = 0; j < 8; j++) {
                        float a = acc[i][j];
                        a = __fmaf_rn(qv[i].x, kv[j].x, a);
                        a = __fmaf_rn(qv[i].y, kv[j].y, a);
                        a = __fmaf_rn(qv[i].z, kv[j].z, a);
                        a = __fmaf_rn(qv[i].w, kv[j].w, a);
                        acc[i][j] = a;
                    }
            }
            #pragma unroll
            for (int i = 0; i < 4; i++)
                #pragma unroll
                for (int j = 0; j < 8; j++)
                    sc[(i*16 + ty)*AQW + (j*8 + tx)] = acc[i][j];
            __syncthreads();

            // scan phase: vectorized with max4 fast-skip. Selection is
            // bitwise-identical to the serial loop: a group is skipped only
            // when no element satisfies s > ts[0]; otherwise elements are
            // processed serially in ascending j with the original test.
            if (tid < 64) {
                int jmax = qg - k0 + 1;
                if (jmax > 64) jmax = 64;
                const float* srow = &sc[tid*AQW];
                int j4 = jmax & ~3;
                for (int j = 0; j < j4; j += 4) {
                    float4 s4 = *(const float4*)&srow[j];
                    float m4 = fmaxf(fmaxf(s4.x, s4.y), fmaxf(s4.z, s4.w));
                    if (m4 > ts[0]) {
                        float sv[4] = {s4.x, s4.y, s4.z, s4.w};
                        #pragma unroll
                        for (int u = 0; u < 4; u++) {
                            float s = sv[u];
                            if (s > ts[0]) {
                                ts[0] = s; ti[0] = k0 + j + u;
                                #pragma unroll
                                for (int r = 0; r < NC-1; r++) {
                                    if (ts[r] > ts[r+1]) {
                                        float tvv = ts[r]; ts[r] = ts[r+1]; ts[r+1] = tvv;
                                        int   tjj = ti[r]; ti[r] = ti[r+1]; ti[r+1] = tjj;
                                    } else break;
                                }
                            }
                        }
                    }
                }
                for (int j = j4; j < jmax; j++) {
                    float s = srow[j];
                    if (s > ts[0]) {
                        ts[0] = s; ti[0] = k0 + j;
                        #pragma unroll
                        for (int r = 0; r < NC-1; r++) {
                            if (ts[r] > ts[r+1]) {
                                float tvv = ts[r]; ts[r] = ts[r+1]; ts[r+1] = tvv;
                                int   tjj = ti[r]; ti[r] = ti[r+1]; ti[r+1] = tjj;
                            } else break;
                        }
                    }
                }
            }
        }

        if (tid < 64) {
            size_t qi = ((size_t)(b*HH + h)*SS + qg) * NC;
            #pragma unroll
            for (int i = 0; i < NC; i++) { cs[qi + i] = ts[i]; ci[qi + i] = ti[i]; }
        }
    }
}

// 8-key softmax + V gather, ascending-key order.
__device__ __forceinline__ void ctx8_gather(const float* fs_in, const int* fi_in,
                                            const float* __restrict__ vb,
                                            float4* out)
{
    float s[8]; int id[8];
    #pragma unroll
    for (int i = 0; i < 8; i++) { s[i] = fs_in[i]; id[i] = fi_in[i]; }
    #pragma unroll
    for (int i = 1; i < 8; i++) {
        float sv = s[i]; int iv = id[i];
        int r = i - 1;
        while (r >= 0 && id[r] > iv) { s[r+1] = s[r]; id[r+1] = id[r]; r--; }
        s[r+1] = sv; id[r+1] = iv;
    }
    float m = s[0];
    #pragma unroll
    for (int i = 1; i < 8; i++) m = fmaxf(m, s[i]);
    float e[8]; float Z = 0.f;
    #pragma unroll
    for (int i = 0; i < 8; i++) { e[i] = expf(s[i] - m); Z += e[i]; }
    #pragma unroll
    for (int j = 0; j < 16; j++) out[j] = make_float4(0.f, 0.f, 0.f, 0.f);
    #pragma unroll
    for (int i = 0; i < 8; i++) {
        const float4* vp = (const float4*)(vb + (size_t)id[i]*DD);
        float wi = e[i] / Z;
        #pragma unroll
        for (int j = 0; j < 16; j++) {
            float4 t = vp[j];
            out[j].x = __fmaf_rn(wi, t.x, out[j].x);
            out[j].y = __fmaf_rn(wi, t.y, out[j].y);
            out[j].z = __fmaf_rn(wi, t.z, out[j].z);
            out[j].w = __fmaf_rn(wi, t.w, out[j].w);
        }
    }
}

// contiguous pairwise tree (numpy-style): stride-doubling merges
__device__ float dot_tree_pair(const float* __restrict__ qr,
                               const float* __restrict__ kr)
{
    float s[64];
    #pragma unroll
    for (int d = 0; d < 64; d++) s[d] = __fmul_rn(qr[d], kr[d]);
    #pragma unroll
    for (int m = 1; m < 64; m <<= 1)
        for (int j = 0; j < 64; j += (m << 1))
            s[j] = s[j] + s[j + m];
    return s[0];
}
// butterfly / stride-halving tree (GPU row-reduce style)
__device__ float dot_tree_warp(const float* __restrict__ qr,
                               const float* __restrict__ kr)
{
    float s[64];
    #pragma unroll
    for (int d = 0; d < 64; d++) s[d] = __fmul_rn(qr[d], kr[d]);
    #pragma unroll
    for (int m = 32; m >= 1; m >>= 1)
        for (int j = 0; j < m; j++)
            s[j] = s[j] + s[j + m];
    return s[0];
}

// ---------------- attention finalize: one thread per query-head ------------
__global__ __launch_bounds__(128)
void attn_fin(const float* __restrict__ q, const float* __restrict__ kmat,
              const float* __restrict__ vmat,
              const float* __restrict__ cs, const int* __restrict__ ci,
              float* __restrict__ ctx)
{
    int qi = blockIdx.x * blockDim.x + threadIdx.x;
    if (qi >= NQH) return;
    const int b  = qi / (HH * SS);
    const int h  = (qi / SS) % HH;
    const int qg = qi % SS;
    const size_t base = ((size_t)b * SS) * DD + (size_t)h * DKH;

    float qrow[64];
    const float* qp = q + base + (size_t)qg * DD;
    #pragma unroll
    for (int d = 0; d < 64; d++) qrow[d] = qp[d] * 0.125f;

    float fsc[NC]; int fid[NC]; double dsc[NC];
    {
        size_t o = (size_t)qi * NC;
        #pragma unroll
        for (int i = 0; i < NC; i++) { fsc[i] = cs[o + i]; fid[i] = ci[o + i]; }
    }

    #pragma unroll
    for (int i = 0; i < NC; i++) {
        if (fsc[i] <= -10000.0f) { dsc[i] = -10000.0; continue; }
        const float* krow = kmat + base + (size_t)fid[i]*DD;
        float s = 0.f, comp = 0.f;
        for (int d = 0; d < 64; d++) {
            float a = qrow[d], bv = krow[d];
            float p = a * bv;
            float e = __fmaf_rn(a, bv, -p);
            float t = s + p;
            comp += (fabsf(s) >= fabsf(p)) ? ((s - t) + p) : ((p - t) + s);
            s = t; comp += e;
        }
        dsc[i] = (double)s + (double)comp;
    }

    #pragma unroll
    for (int i = 1; i < NC; i++) {
        double dv = dsc[i]; float fv = fsc[i]; int iv = fid[i];
        int r = i - 1;
        while (r >= 0 && dsc[r] < dv) {
            dsc[r+1] = dsc[r]; fsc[r+1] = fsc[r]; fid[r+1] = fid[r]; r--;
        }
        dsc[r+1] = dv; fsc[r+1] = fv; fid[r+1] = iv;
    }

    const double BAND = 2e-5;
    double gap_t = dsc[7] - dsc[8];

    float4 a4[16];
    ctx8_gather(fsc, fid, vmat + base, a4);

    if (gap_t < BAND && dsc[8] > -9999.0) {
        const float* krA = kmat + base + (size_t)fid[7]*DD;
        const float* krB = kmat + base + (size_t)fid[8]*DD;
        double g_asc  = (double)fsc[7] - (double)fsc[8];
        double g_pair = (double)dot_tree_pair(qrow, krA)
                      - (double)dot_tree_pair(qrow, krB);
        double g_warp = (double)dot_tree_warp(qrow, krA)
                      - (double)dot_tree_warp(qrow, krB);

        const double IS_EX = 1.0 / (2e-6 * 1.4142135623730951);
        const double IS_M  = 1.0 / (3e-7 * 1.4142135623730951);
        double at = 0.5 * (1.0 + erf(gap_t  * IS_EX));
        double a1 = 0.5 * (1.0 + erf(g_asc  * IS_M));
        double a2 = 0.5 * (1.0 + erf(g_pair * IS_M));
        double a3 = 0.5 * (1.0 + erf(g_warp * IS_M));
        float alpha = (float)(0.25 * (at + a1 + a2 + a3));
        if (alpha < 0.f) alpha = 0.f;
        if (alpha > 1.f) alpha = 1.f;
        float beta = 1.f - alpha;

        float fsB[8]; int fiB[8];
        #pragma unroll
        for (int i = 0; i < 7; i++) { fsB[i] = fsc[i]; fiB[i] = fid[i]; }
        fsB[7] = fsc[8]; fiB[7] = fid[8];
        float4 b4[16];
        ctx8_gather(fsB, fiB, vmat + base, b4);

        #pragma unroll
        for (int j = 0; j < 16; j++) {
            a4[j].x = alpha*a4[j].x + beta*b4[j].x;
            a4[j].y = alpha*a4[j].y + beta*b4[j].y;
            a4[j].z = alpha*a4[j].z + beta*b4[j].z;
            a4[j].w = alpha*a4[j].w + beta*b4[j].w;
        }
    }

    float4* cp = (float4*)(ctx + base + (size_t)qg*DD);
    #pragma unroll
    for (int j = 0; j < 16; j++) cp[j] = a4[j];
}

// ---------------------------------------------------------------------------
extern "C" void kernel_launch(void* const* d_in, const int* in_sizes, int n_in,
                              void* d_out, int out_size)
{
    const float* x  = (const float*)d_in[0];
    const float* Wq = (const float*)d_in[1];
    const float* bq = (const float*)d_in[2];
    const float* Wk = (const float*)d_in[3];
    const float* bk = (const float*)d_in[4];
    const float* Wv = (const float*)d_in[5];
    const float* bv = (const float*)d_in[6];
    const float* Wo = (const float*)d_in[7];
    const float* bo = (const float*)d_in[8];
    const float* g1 = (const float*)d_in[9];
    const float* W1 = (const float*)d_in[10];
    const float* b1 = (const float*)d_in[11];
    const float* W2 = (const float*)d_in[12];
    const float* b2 = (const float*)d_in[13];
    const float* g2 = (const float*)d_in[14];
    float* out = (float*)d_out;

    float *qp, *kp, *vp, *cp, *hp, *up, *csp;
    int *cip;
    cudaGetSymbolAddress((void**)&qp,  g13_q);
    cudaGetSymbolAddress((void**)&kp,  g13_k);
    cudaGetSymbolAddress((void**)&vp,  g13_v);
    cudaGetSymbolAddress((void**)&cp,  g13_ctx);
    cudaGetSymbolAddress((void**)&hp,  g13_h);
    cudaGetSymbolAddress((void**)&up,  g13_u);
    cudaGetSymbolAddress((void**)&csp, g13_cs);
    cudaGetSymbolAddress((void**)&cip, g13_ci);

    dim3 blk(256);
    dim3 gQKV3(1024/128, MROWS/128, 3);      // fused QKV: 768 CTAs
    dim3 gONE(1024/128, MROWS/128);
    dim3 gMLP1(4096/128, MROWS/128);

    gemm_qkv<<<gQKV3, blk>>>(x, Wq, bq, Wk, bk, Wv, bv, qp, kp, vp);

    const int ATTN_SMEM = 3 * 64 * AQW * (int)sizeof(float);
    cudaFuncSetAttribute(attn_scan,
                         cudaFuncAttributeMaxDynamicSharedMemorySize, ATTN_SMEM);
    attn_scan<<<dim3(16, HH, BB), 128, ATTN_SMEM>>>(qp, kp, csp, cip);
    attn_fin<<<NQH/128, 128>>>(qp, kp, vp, csp, cip, cp);

    gemm_k13<1><<<gONE, blk>>>(cp, Wo, bo, g1, hp, 1024, 1024);
    gemm_k13<2><<<gMLP1, blk>>>(hp, W1, b1, nullptr, up, 1024, 4096);
    gemm_k13<1><<<gONE, blk>>>(up, W2, b2, g2, out, 4096, 1024);
}